// round 13
// baseline (speedup 1.0000x reference)

#include <cuda_runtime.h>

#define BSZ 8192
#define DIM 128
#define BM 64
#define BN 64
#define NBLK (BSZ / BM)     // 128
#define NTILES (BSZ / BN)   // 128
#define SM_STRIDE 68        // 17*4: float4-aligned, conflict-reduced

// scratch (device globals — no allocation)
__device__ float g_xn[BSZ * DIM];
__device__ int   g_lab[BSZ];
__device__ int   g_n1;
__device__ float g_partials[NBLK];

// ---------------------------------------------------------------------------
// Kernel 1: count class-1 labels
// ---------------------------------------------------------------------------
__global__ void count_kernel(const long long* __restrict__ label) {
    __shared__ int sh[256];
    int tid = threadIdx.x;
    int acc = 0;
    for (int i = tid; i < BSZ; i += 256) acc += (int)label[i];
    sh[tid] = acc;
    __syncthreads();
    for (int s = 128; s > 0; s >>= 1) {
        if (tid < s) sh[tid] += sh[tid + s];
        __syncthreads();
    }
    if (tid == 0) g_n1 = sh[0];
}

// ---------------------------------------------------------------------------
// Kernel 2: L2-normalize rows (one warp per row), stash labels as int
// ---------------------------------------------------------------------------
__global__ void normalize_kernel(const float* __restrict__ data,
                                 const long long* __restrict__ label) {
    int warp = threadIdx.x >> 5;
    int lane = threadIdx.x & 31;
    int row  = blockIdx.x * 8 + warp;

    float4 v = ((const float4*)(data + (size_t)row * DIM))[lane];
    float ss = v.x * v.x + v.y * v.y + v.z * v.z + v.w * v.w;
#pragma unroll
    for (int o = 16; o; o >>= 1) ss += __shfl_xor_sync(0xffffffffu, ss, o);

    float n   = fmaxf(sqrtf(ss), 1e-12f);
    float inv = 1.0f / n;
    float4 o4 = make_float4(v.x * inv, v.y * inv, v.z * inv, v.w * inv);
    ((float4*)(g_xn + (size_t)row * DIM))[lane] = o4;

    if (lane == 0) g_lab[row] = (int)label[row];
}

// ---------------------------------------------------------------------------
// Kernel 3: fused GEMM (x @ x^T) + streaming per-row reductions
//   per row i:  Z = sum e^{l-s},  T = sum e^{l-s} l,  S = sum l,
//               E = sum_{same} e^{l-s},  Q = sum_{same} l
//   row loss:   qs + T/Z - qd*S - (qs-qd)*Q - (E/Z)/c      (lse & log qd cancel)
// ---------------------------------------------------------------------------
__global__ __launch_bounds__(256, 1)
void main_kernel(const float* __restrict__ scale_ptr) {
    extern __shared__ float sm[];
    float* As   = sm;                       // [DIM][SM_STRIDE], A^T
    float* Bs   = sm + DIM * SM_STRIDE;     // [DIM][SM_STRIDE], B^T
    int*   labB = (int*)(sm + 2 * DIM * SM_STRIDE);

    const int tid = threadIdx.x;
    const int tx  = tid & 15;               // column group
    const int ty  = tid >> 4;               // row group
    const int rowbase = blockIdx.x * BM;
    const float s = expf(*scale_ptr);

    // Load A tile once, transposed (global coalesced)
    for (int i = tid; i < BM * DIM; i += 256) {
        int r = i >> 7, k = i & (DIM - 1);
        As[k * SM_STRIDE + r] = g_xn[(size_t)(rowbase + r) * DIM + k];
    }

    int labR[4];
#pragma unroll
    for (int j = 0; j < 4; j++) labR[j] = g_lab[rowbase + ty * 4 + j];

    float accZ[4] = {0}, accT[4] = {0}, accS[4] = {0}, accE[4] = {0}, accQ[4] = {0};

    for (int t = 0; t < NTILES; t++) {
        __syncthreads();                    // As ready / Bs free to overwrite
        const int colbase = t * BN;
        for (int i = tid; i < BN * DIM; i += 256) {
            int r = i >> 7, k = i & (DIM - 1);
            Bs[k * SM_STRIDE + r] = g_xn[(size_t)(colbase + r) * DIM + k];
        }
        if (tid < BN) labB[tid] = g_lab[colbase + tid];
        __syncthreads();

        float acc[4][4];
#pragma unroll
        for (int j = 0; j < 4; j++)
#pragma unroll
            for (int c = 0; c < 4; c++) acc[j][c] = 0.f;

#pragma unroll 8
        for (int k = 0; k < DIM; k++) {
            float4 a4 = *(const float4*)&As[k * SM_STRIDE + ty * 4];
            float4 b4 = *(const float4*)&Bs[k * SM_STRIDE + tx * 4];
            float av[4] = {a4.x, a4.y, a4.z, a4.w};
            float bv[4] = {b4.x, b4.y, b4.z, b4.w};
#pragma unroll
            for (int j = 0; j < 4; j++)
#pragma unroll
                for (int c = 0; c < 4; c++)
                    acc[j][c] = fmaf(av[j], bv[c], acc[j][c]);
        }

        int lc[4];
#pragma unroll
        for (int c = 0; c < 4; c++) lc[c] = labB[tx * 4 + c];

#pragma unroll
        for (int j = 0; j < 4; j++) {
#pragma unroll
            for (int c = 0; c < 4; c++) {
                float l = s * acc[j][c];
                float e = __expf(l - s);
                accZ[j] += e;
                accT[j] = fmaf(e, l, accT[j]);
                accS[j] += l;
                if (lc[c] == labR[j]) { accE[j] += e; accQ[j] += l; }
            }
        }
    }

    // Reduce across the 16-thread column group (lanes [0..15] / [16..31] share ty)
#pragma unroll
    for (int j = 0; j < 4; j++) {
#pragma unroll
        for (int o = 8; o; o >>= 1) {
            accZ[j] += __shfl_xor_sync(0xffffffffu, accZ[j], o);
            accT[j] += __shfl_xor_sync(0xffffffffu, accT[j], o);
            accS[j] += __shfl_xor_sync(0xffffffffu, accS[j], o);
            accE[j] += __shfl_xor_sync(0xffffffffu, accE[j], o);
            accQ[j] += __shfl_xor_sync(0xffffffffu, accQ[j], o);
        }
    }

    __shared__ float red[16];
    if (tx == 0) {
        const int n1 = g_n1;
        double total = 0.0;
#pragma unroll
        for (int j = 0; j < 4; j++) {
            int ci = labR[j] ? n1 : (BSZ - n1);
            double cd  = (double)ci;
            double ic  = 1.0 / cd;
            double eic = exp(ic);
            double Dd  = cd * eic + (double)(BSZ - ci);
            double qd  = 1.0 / Dd;
            double qs  = eic / Dd;
            double Z   = (double)accZ[j];
            double v   = qs + (double)accT[j] / Z
                       - qd * (double)accS[j]
                       - (qs - qd) * (double)accQ[j]
                       - ((double)accE[j] / Z) * ic;
            total += v;
        }
        red[ty] = (float)total;
    }
    __syncthreads();
    if (tid == 0) {
        float sum = 0.f;
#pragma unroll
        for (int i = 0; i < 16; i++) sum += red[i];
        g_partials[blockIdx.x] = sum;
    }
}

// ---------------------------------------------------------------------------
// Kernel 4: deterministic final reduction
// ---------------------------------------------------------------------------
__global__ void final_kernel(float* __restrict__ out) {
    __shared__ float sh[128];
    int tid = threadIdx.x;
    sh[tid] = g_partials[tid];
    __syncthreads();
    for (int s = 64; s > 0; s >>= 1) {
        if (tid < s) sh[tid] += sh[tid + s];
        __syncthreads();
    }
    if (tid == 0) out[0] = sh[0] / (2.0f * (float)BSZ);
}

// ---------------------------------------------------------------------------
extern "C" void kernel_launch(void* const* d_in, const int* in_sizes, int n_in,
                              void* d_out, int out_size) {
    const float*     data  = (const float*)d_in[0];
    const float*     scale = (const float*)d_in[1];
    const long long* label = (const long long*)d_in[2];
    float*           out   = (float*)d_out;

    size_t smem = (size_t)(2 * DIM * SM_STRIDE) * sizeof(float) + BN * sizeof(int);
    cudaFuncSetAttribute(main_kernel, cudaFuncAttributeMaxDynamicSharedMemorySize,
                         (int)smem);

    count_kernel<<<1, 256>>>(label);
    normalize_kernel<<<BSZ / 8, 256>>>(data, label);
    main_kernel<<<NBLK, 256, smem>>>(scale);
    final_kernel<<<1, 128>>>(out);
}

// round 14
// speedup vs baseline: 1.7742x; 1.7742x over previous
#include <cuda_runtime.h>

#define BSZ 8192
#define DIM 128
#define BM 64
#define BN 128
#define NBLK (BSZ / BM)     // 128
#define NTILES (BSZ / BN)   // 64
#define SA 68               // As stride (words), R1 value
#define SB 132              // Bs stride (words): 128 cols + 4 pad

// scratch (device globals — no allocation; R1-proven minimal set)
__device__ float g_xn[BSZ * DIM];
__device__ int   g_lab[BSZ];
__device__ int   g_n1;
__device__ float g_partials[NBLK];

// ---------------------------------------------------------------------------
// Kernel 1: count class-1 labels (verbatim R1)
// ---------------------------------------------------------------------------
__global__ void count_kernel(const long long* __restrict__ label) {
    __shared__ int sh[256];
    int tid = threadIdx.x;
    int acc = 0;
    for (int i = tid; i < BSZ; i += 256) acc += (int)label[i];
    sh[tid] = acc;
    __syncthreads();
    for (int s = 128; s > 0; s >>= 1) {
        if (tid < s) sh[tid] += sh[tid + s];
        __syncthreads();
    }
    if (tid == 0) g_n1 = sh[0];
}

// ---------------------------------------------------------------------------
// Kernel 2: L2-normalize rows (verbatim R1)
// ---------------------------------------------------------------------------
__global__ void normalize_kernel(const float* __restrict__ data,
                                 const long long* __restrict__ label) {
    int warp = threadIdx.x >> 5;
    int lane = threadIdx.x & 31;
    int row  = blockIdx.x * 8 + warp;

    float4 v = ((const float4*)(data + (size_t)row * DIM))[lane];
    float ss = v.x * v.x + v.y * v.y + v.z * v.z + v.w * v.w;
#pragma unroll
    for (int o = 16; o; o >>= 1) ss += __shfl_xor_sync(0xffffffffu, ss, o);

    float n   = fmaxf(sqrtf(ss), 1e-12f);
    float inv = 1.0f / n;
    float4 o4 = make_float4(v.x * inv, v.y * inv, v.z * inv, v.w * inv);
    ((float4*)(g_xn + (size_t)row * DIM))[lane] = o4;

    if (lane == 0) g_lab[row] = (int)label[row];
}

// ---------------------------------------------------------------------------
// Kernel 3: fused GEMM + streaming row reductions. R1 structure; deltas:
// BN=128 (64 chunks, half the barriers) and 4x8 microtile (better FMA:LDS).
// ---------------------------------------------------------------------------
__global__ __launch_bounds__(256, 1)
void main_kernel(const float* __restrict__ scale_ptr) {
    extern __shared__ float sm[];
    float* As   = sm;                       // [DIM][SA], A^T
    float* Bs   = sm + DIM * SA;            // [DIM][SB], B^T
    int*   labB = (int*)(sm + DIM * SA + DIM * SB);

    const int tid = threadIdx.x;
    const int tx  = tid & 15;               // column group
    const int ty  = tid >> 4;               // row group (rows ty*4..ty*4+3)
    const int rowbase = blockIdx.x * BM;
    const float s = expf(*scale_ptr);

    // Load A tile once, transposed (global coalesced) — R1 pattern
    for (int i = tid; i < BM * DIM; i += 256) {
        int r = i >> 7, k = i & (DIM - 1);
        As[k * SA + r] = g_xn[(size_t)(rowbase + r) * DIM + k];
    }

    int labR[4];
#pragma unroll
    for (int j = 0; j < 4; j++) labR[j] = g_lab[rowbase + ty * 4 + j];

    float accZ[4] = {0}, accT[4] = {0}, accS[4] = {0}, accE[4] = {0}, accQ[4] = {0};

    for (int t = 0; t < NTILES; t++) {
        __syncthreads();                    // previous chunk's Bs readers done
        const int colbase = t * BN;
        for (int i = tid; i < BN * DIM; i += 256) {
            int r = i >> 7, k = i & (DIM - 1);
            Bs[k * SB + r] = g_xn[(size_t)(colbase + r) * DIM + k];
        }
        if (tid < BN) labB[tid] = g_lab[colbase + tid];
        __syncthreads();                    // Bs + labB ready

        float acc[4][8];
#pragma unroll
        for (int j = 0; j < 4; j++)
#pragma unroll
            for (int c = 0; c < 8; c++) acc[j][c] = 0.f;

#pragma unroll 8
        for (int k = 0; k < DIM; k++) {
            float4 a4  = *(const float4*)&As[k * SA + ty * 4];
            float4 b4a = *(const float4*)&Bs[k * SB + tx * 4];
            float4 b4b = *(const float4*)&Bs[k * SB + 64 + tx * 4];
            float av[4] = {a4.x, a4.y, a4.z, a4.w};
            float bv[8] = {b4a.x, b4a.y, b4a.z, b4a.w, b4b.x, b4b.y, b4b.z, b4b.w};
#pragma unroll
            for (int j = 0; j < 4; j++)
#pragma unroll
                for (int c = 0; c < 8; c++)
                    acc[j][c] = fmaf(av[j], bv[c], acc[j][c]);
        }

        int lc[8];
#pragma unroll
        for (int c = 0; c < 8; c++) lc[c] = labB[(c >> 2) * 64 + tx * 4 + (c & 3)];

#pragma unroll
        for (int j = 0; j < 4; j++) {
#pragma unroll
            for (int c = 0; c < 8; c++) {
                float l = s * acc[j][c];
                float e = __expf(l - s);
                accZ[j] += e;
                accT[j] = fmaf(e, l, accT[j]);
                accS[j] += l;
                if (lc[c] == labR[j]) { accE[j] += e; accQ[j] += l; }
            }
        }
    }

    // Reduce across the 16-thread column group (R1 pattern)
#pragma unroll
    for (int j = 0; j < 4; j++) {
#pragma unroll
        for (int o = 8; o; o >>= 1) {
            accZ[j] += __shfl_xor_sync(0xffffffffu, accZ[j], o);
            accT[j] += __shfl_xor_sync(0xffffffffu, accT[j], o);
            accS[j] += __shfl_xor_sync(0xffffffffu, accS[j], o);
            accE[j] += __shfl_xor_sync(0xffffffffu, accE[j], o);
            accQ[j] += __shfl_xor_sync(0xffffffffu, accQ[j], o);
        }
    }

    __shared__ float red[16];
    if (tx == 0) {
        const int n1 = g_n1;
        double total = 0.0;
#pragma unroll
        for (int j = 0; j < 4; j++) {
            int ci = labR[j] ? n1 : (BSZ - n1);
            double cd  = (double)ci;
            double ic  = 1.0 / cd;
            double eic = exp(ic);
            double Dd  = cd * eic + (double)(BSZ - ci);
            double qd  = 1.0 / Dd;
            double qs  = eic / Dd;
            double Z   = (double)accZ[j];
            double v   = qs + (double)accT[j] / Z
                       - qd * (double)accS[j]
                       - (qs - qd) * (double)accQ[j]
                       - ((double)accE[j] / Z) * ic;
            total += v;
        }
        red[ty] = (float)total;
    }
    __syncthreads();
    if (tid == 0) {
        float sum = 0.f;
#pragma unroll
        for (int i = 0; i < 16; i++) sum += red[i];
        g_partials[blockIdx.x] = sum;
    }
}

// ---------------------------------------------------------------------------
// Kernel 4: deterministic final reduction (verbatim R1)
// ---------------------------------------------------------------------------
__global__ void final_kernel(float* __restrict__ out) {
    __shared__ float sh[128];
    int tid = threadIdx.x;
    sh[tid] = g_partials[tid];
    __syncthreads();
    for (int s = 64; s > 0; s >>= 1) {
        if (tid < s) sh[tid] += sh[tid + s];
        __syncthreads();
    }
    if (tid == 0) out[0] = sh[0] / (2.0f * (float)BSZ);
}

// ---------------------------------------------------------------------------
extern "C" void kernel_launch(void* const* d_in, const int* in_sizes, int n_in,
                              void* d_out, int out_size) {
    const float*     data  = (const float*)d_in[0];
    const float*     scale = (const float*)d_in[1];
    const long long* label = (const long long*)d_in[2];
    float*           out   = (float*)d_out;

    size_t smem = (size_t)(DIM * SA + DIM * SB) * sizeof(float) + BN * sizeof(int);
    cudaFuncSetAttribute(main_kernel, cudaFuncAttributeMaxDynamicSharedMemorySize,
                         (int)smem);

    count_kernel<<<1, 256>>>(label);
    normalize_kernel<<<BSZ / 8, 256>>>(data, label);
    main_kernel<<<NBLK, 256, smem>>>(scale);
    final_kernel<<<1, 128>>>(out);
}

// round 15
// speedup vs baseline: 1.7953x; 1.0119x over previous
#include <cuda_runtime.h>
#include <cstdint>

#define BSZ 8192
#define DIM 128
#define BM 64
#define BN 128
#define NBLK (BSZ / BM)     // 128
#define NTILES (BSZ / BN)   // 64
#define SA 68               // As stride (words), R1 value
#define SB 132              // Bs stride (words): 128 cols + 4 pad

typedef unsigned long long ull;

// scratch (device globals — no allocation; R1-proven minimal set)
__device__ float g_xn[BSZ * DIM];
__device__ int   g_lab[BSZ];
__device__ int   g_n1;
__device__ float g_partials[NBLK];

// packed helpers: FMA2 lanes = two adjacent rows sharing one B scalar
#define FMA2(d, a, b) asm("fma.rn.f32x2 %0, %1, %2, %0;" : "+l"(d) : "l"(a), "l"(b))
__device__ __forceinline__ ull dup2(float b) {
    ull r;
    asm("mov.b64 %0, {%1, %1};" : "=l"(r) : "r"(__float_as_uint(b)));
    return r;
}

// ---------------------------------------------------------------------------
// Kernel 1: count class-1 labels (verbatim R1)
// ---------------------------------------------------------------------------
__global__ void count_kernel(const long long* __restrict__ label) {
    __shared__ int sh[256];
    int tid = threadIdx.x;
    int acc = 0;
    for (int i = tid; i < BSZ; i += 256) acc += (int)label[i];
    sh[tid] = acc;
    __syncthreads();
    for (int s = 128; s > 0; s >>= 1) {
        if (tid < s) sh[tid] += sh[tid + s];
        __syncthreads();
    }
    if (tid == 0) g_n1 = sh[0];
}

// ---------------------------------------------------------------------------
// Kernel 2: L2-normalize rows (verbatim R1)
// ---------------------------------------------------------------------------
__global__ void normalize_kernel(const float* __restrict__ data,
                                 const long long* __restrict__ label) {
    int warp = threadIdx.x >> 5;
    int lane = threadIdx.x & 31;
    int row  = blockIdx.x * 8 + warp;

    float4 v = ((const float4*)(data + (size_t)row * DIM))[lane];
    float ss = v.x * v.x + v.y * v.y + v.z * v.z + v.w * v.w;
#pragma unroll
    for (int o = 16; o; o >>= 1) ss += __shfl_xor_sync(0xffffffffu, ss, o);

    float n   = fmaxf(sqrtf(ss), 1e-12f);
    float inv = 1.0f / n;
    float4 o4 = make_float4(v.x * inv, v.y * inv, v.z * inv, v.w * inv);
    ((float4*)(g_xn + (size_t)row * DIM))[lane] = o4;

    if (lane == 0) g_lab[row] = (int)label[row];
}

// ---------------------------------------------------------------------------
// Kernel 3: fused GEMM + streaming row reductions. R14 structure; single
// delta: inner loop uses fma.rn.f32x2 packed across adjacent ROWS (lanes =
// rows j,j+1; B scalar duplicated). Bitwise-identical fp32 arithmetic.
// ---------------------------------------------------------------------------
__global__ __launch_bounds__(256, 1)
void main_kernel(const float* __restrict__ scale_ptr) {
    extern __shared__ float sm[];
    float* As   = sm;                       // [DIM][SA], A^T
    float* Bs   = sm + DIM * SA;            // [DIM][SB], B^T
    int*   labB = (int*)(sm + DIM * SA + DIM * SB);

    const int tid = threadIdx.x;
    const int tx  = tid & 15;               // column group
    const int ty  = tid >> 4;               // row group (rows ty*4..ty*4+3)
    const int rowbase = blockIdx.x * BM;
    const float s = expf(*scale_ptr);

    // Load A tile once, transposed (global coalesced) — R1 pattern
    for (int i = tid; i < BM * DIM; i += 256) {
        int r = i >> 7, k = i & (DIM - 1);
        As[k * SA + r] = g_xn[(size_t)(rowbase + r) * DIM + k];
    }

    int labR[4];
#pragma unroll
    for (int j = 0; j < 4; j++) labR[j] = g_lab[rowbase + ty * 4 + j];

    float accZ[4] = {0}, accT[4] = {0}, accS[4] = {0}, accE[4] = {0}, accQ[4] = {0};

    for (int t = 0; t < NTILES; t++) {
        __syncthreads();                    // previous chunk's Bs readers done
        const int colbase = t * BN;
        for (int i = tid; i < BN * DIM; i += 256) {
            int r = i >> 7, k = i & (DIM - 1);
            Bs[k * SB + r] = g_xn[(size_t)(colbase + r) * DIM + k];
        }
        if (tid < BN) labB[tid] = g_lab[colbase + tid];
        __syncthreads();                    // Bs + labB ready

        // packed accumulators: acc2[p][c] lanes = rows (ty*4+2p, ty*4+2p+1)
        ull acc2[2][8];
#pragma unroll
        for (int p = 0; p < 2; p++)
#pragma unroll
            for (int c = 0; c < 8; c++) acc2[p][c] = 0ull;

#pragma unroll 8
        for (int k = 0; k < DIM; k++) {
            float4 a4  = *(const float4*)&As[k * SA + ty * 4];
            float4 b4a = *(const float4*)&Bs[k * SB + tx * 4];
            float4 b4b = *(const float4*)&Bs[k * SB + 64 + tx * 4];
            ull a01, a23;
            asm("mov.b64 %0, {%1, %2};" : "=l"(a01)
                : "r"(__float_as_uint(a4.x)), "r"(__float_as_uint(a4.y)));
            asm("mov.b64 %0, {%1, %2};" : "=l"(a23)
                : "r"(__float_as_uint(a4.z)), "r"(__float_as_uint(a4.w)));
            ull bb[8];
            bb[0] = dup2(b4a.x); bb[1] = dup2(b4a.y);
            bb[2] = dup2(b4a.z); bb[3] = dup2(b4a.w);
            bb[4] = dup2(b4b.x); bb[5] = dup2(b4b.y);
            bb[6] = dup2(b4b.z); bb[7] = dup2(b4b.w);
#pragma unroll
            for (int c = 0; c < 8; c++) {
                FMA2(acc2[0][c], a01, bb[c]);
                FMA2(acc2[1][c], a23, bb[c]);
            }
        }

        // unpack to the R14 epilogue view
        float acc[4][8];
#pragma unroll
        for (int p = 0; p < 2; p++)
#pragma unroll
            for (int c = 0; c < 8; c++) {
                acc[2 * p + 0][c] = __uint_as_float((unsigned)(acc2[p][c] & 0xffffffffu));
                acc[2 * p + 1][c] = __uint_as_float((unsigned)(acc2[p][c] >> 32));
            }

        int lc[8];
#pragma unroll
        for (int c = 0; c < 8; c++) lc[c] = labB[(c >> 2) * 64 + tx * 4 + (c & 3)];

#pragma unroll
        for (int j = 0; j < 4; j++) {
#pragma unroll
            for (int c = 0; c < 8; c++) {
                float l = s * acc[j][c];
                float e = __expf(l - s);
                accZ[j] += e;
                accT[j] = fmaf(e, l, accT[j]);
                accS[j] += l;
                if (lc[c] == labR[j]) { accE[j] += e; accQ[j] += l; }
            }
        }
    }

    // Reduce across the 16-thread column group (R1 pattern)
#pragma unroll
    for (int j = 0; j < 4; j++) {
#pragma unroll
        for (int o = 8; o; o >>= 1) {
            accZ[j] += __shfl_xor_sync(0xffffffffu, accZ[j], o);
            accT[j] += __shfl_xor_sync(0xffffffffu, accT[j], o);
            accS[j] += __shfl_xor_sync(0xffffffffu, accS[j], o);
            accE[j] += __shfl_xor_sync(0xffffffffu, accE[j], o);
            accQ[j] += __shfl_xor_sync(0xffffffffu, accQ[j], o);
        }
    }

    __shared__ float red[16];
    if (tx == 0) {
        const int n1 = g_n1;
        double total = 0.0;
#pragma unroll
        for (int j = 0; j < 4; j++) {
            int ci = labR[j] ? n1 : (BSZ - n1);
            double cd  = (double)ci;
            double ic  = 1.0 / cd;
            double eic = exp(ic);
            double Dd  = cd * eic + (double)(BSZ - ci);
            double qd  = 1.0 / Dd;
            double qs  = eic / Dd;
            double Z   = (double)accZ[j];
            double v   = qs + (double)accT[j] / Z
                       - qd * (double)accS[j]
                       - (qs - qd) * (double)accQ[j]
                       - ((double)accE[j] / Z) * ic;
            total += v;
        }
        red[ty] = (float)total;
    }
    __syncthreads();
    if (tid == 0) {
        float sum = 0.f;
#pragma unroll
        for (int i = 0; i < 16; i++) sum += red[i];
        g_partials[blockIdx.x] = sum;
    }
}

// ---------------------------------------------------------------------------
// Kernel 4: deterministic final reduction (verbatim R1)
// ---------------------------------------------------------------------------
__global__ void final_kernel(float* __restrict__ out) {
    __shared__ float sh[128];
    int tid = threadIdx.x;
    sh[tid] = g_partials[tid];
    __syncthreads();
    for (int s = 64; s > 0; s >>= 1) {
        if (tid < s) sh[tid] += sh[tid + s];
        __syncthreads();
    }
    if (tid == 0) out[0] = sh[0] / (2.0f * (float)BSZ);
}

// ---------------------------------------------------------------------------
extern "C" void kernel_launch(void* const* d_in, const int* in_sizes, int n_in,
                              void* d_out, int out_size) {
    const float*     data  = (const float*)d_in[0];
    const float*     scale = (const float*)d_in[1];
    const long long* label = (const long long*)d_in[2];
    float*           out   = (float*)d_out;

    size_t smem = (size_t)(DIM * SA + DIM * SB) * sizeof(float) + BN * sizeof(int);
    cudaFuncSetAttribute(main_kernel, cudaFuncAttributeMaxDynamicSharedMemorySize,
                         (int)smem);

    count_kernel<<<1, 256>>>(label);
    normalize_kernel<<<BSZ / 8, 256>>>(data, label);
    main_kernel<<<NBLK, 256, smem>>>(scale);
    final_kernel<<<1, 128>>>(out);
}